// round 13
// baseline (speedup 1.0000x reference)
#include <cuda_runtime.h>
#include <cuda_fp16.h>
#include <math.h>
#include <stdint.h>

#define Bb 16
#define Ss 512
#define Hh 768
#define Ll 12
#define NHh 12
#define FFf 3072
#define Mm (Bb*Ss)
#define GRIDP 296

__device__ float g_x [(size_t)Mm*Hh];
__device__ float g_t [(size_t)Mm*Hh];
__device__ __align__(16) __half g_ah [(size_t)Mm*Hh];
__device__ __align__(16) __half g_ch [(size_t)Mm*Hh];
__device__ __align__(16) __half g_qh [(size_t)Mm*Hh];
__device__ __align__(16) __half g_kh [(size_t)Mm*Hh];
__device__ __align__(16) __half g_vth[(size_t)Mm*Hh];
__device__ __align__(16) __half g_fh [(size_t)Mm*FFf];
#define WLSTR 7077888ULL
__device__ __align__(16) __half g_wh[WLSTR*Ll];
#define OQW 0ULL
#define OKW 589824ULL
#define OVW 1179648ULL
#define OOW 1769472ULL
#define OIW 2359296ULL
#define ODW 4718592ULL

__device__ __forceinline__ uint32_t smem_u32(const void* p){
    uint32_t a; asm("{ .reg .u64 t; cvta.to.shared.u64 t, %1; cvt.u32.u64 %0, t; }":"=r"(a):"l"(p)); return a;
}
#define CP16(dst,src) asm volatile("cp.async.cg.shared.global [%0], [%1], 16;"::"r"(dst),"l"(src))
#define CP_COMMIT()   asm volatile("cp.async.commit_group;")
#define CP_WAIT1()    asm volatile("cp.async.wait_group 1;")
#define CP_WAIT0()    asm volatile("cp.async.wait_group 0;")
#define LDSM4(R,a) asm volatile("ldmatrix.sync.aligned.m8n8.x4.shared.b16 {%0,%1,%2,%3}, [%4];" \
    : "=r"((R)[0]),"=r"((R)[1]),"=r"((R)[2]),"=r"((R)[3]) : "r"(a))
#define MMA(C,A,b0,b1) asm volatile( \
    "mma.sync.aligned.m16n8k16.row.col.f32.f16.f16.f32 {%0,%1,%2,%3}, {%4,%5,%6,%7}, {%8,%9}, {%0,%1,%2,%3};" \
    : "+f"((C)[0]),"+f"((C)[1]),"+f"((C)[2]),"+f"((C)[3]) \
    : "r"((A)[0]),"r"((A)[1]),"r"((A)[2]),"r"((A)[3]), "r"(b0),"r"(b1))

__device__ __forceinline__ uint32_t packh2(float a, float b){
    __half2 h = __floats2half2_rn(a,b);
    return *(uint32_t*)&h;
}

// ---- all-weights staging: W[K,N] fp32 -> Wt[N,K] fp16, ONE launch ----
__global__ void w_stage_all(const float* __restrict__ Wq, const float* __restrict__ Wk,
                            const float* __restrict__ Wv, const float* __restrict__ Wo,
                            const float* __restrict__ Wi, const float* __restrict__ Wd,
                            __half* __restrict__ th){
    __shared__ float tile[32][33];
    int bi=blockIdx.x;
    const float* W; size_t ob; int N,K,n0,k0;
    if(bi<27648){
        int w=bi/6912, local=bi%6912;
        W = (w==0)?Wq:(w==1)?Wk:(w==2)?Wv:Wo;
        ob = (size_t)w*589824ULL;
        N=768; K=768;
        int l=local/576, rem=local%576;
        W += (size_t)l*589824ULL; ob += (size_t)l*WLSTR;
        n0=(rem%24)*32; k0=(rem/24)*32;
    } else if(bi<55296){
        int local=bi-27648;
        W=Wi; ob=OIW; N=3072; K=768;
        int l=local/2304, rem=local%2304;
        W += (size_t)l*2359296ULL; ob += (size_t)l*WLSTR;
        n0=(rem%96)*32; k0=(rem/96)*32;
    } else {
        int local=bi-55296;
        W=Wd; ob=ODW; N=768; K=3072;
        int l=local/2304, rem=local%2304;
        W += (size_t)l*2359296ULL; ob += (size_t)l*WLSTR;
        n0=(rem%24)*32; k0=(rem/24)*32;
    }
    int tx=threadIdx.x&31, ty=threadIdx.x>>5;
    for(int i=ty;i<32;i+=8) tile[i][tx]=W[(size_t)(k0+i)*N+n0+tx];
    __syncthreads();
    for(int i=ty;i<32;i+=8){
        size_t o=ob+(size_t)(n0+i)*K+k0+tx;
        th[o]=__float2half_rn(tile[tx][i]);
    }
}

// ---- fp16 persistent tensor-core GEMM, CTA 128x128 (QKV / Wi) ----
#define ABYTES 18432
#define STG (2*ABYTES)
#define SMEMSZ (3*STG)
__global__ void __launch_bounds__(256,2) mma_gemm(
    const __half* __restrict__ A, const __half* __restrict__ Bh,
    const float* __restrict__ bias, const float* __restrict__ bias2, const float* __restrict__ bias3,
    __half* __restrict__ Ch, __half* __restrict__ C2h, __half* __restrict__ C3h,
    int M, int N, int K, int mode)   // mode 3=gelu fp16, 7=QKV
{
    extern __shared__ __align__(128) char smem[];
    uint32_t sb = smem_u32(smem);
    int tid=threadIdx.x, lane=tid&31, wid=tid>>5;
    int nch=K>>6;
    int wm=wid>>2, wn=wid&3;
    int ntn=N>>7, ntiles=(M>>7)*ntn;
    uint32_t aRowB = (uint32_t)(wm*64 + (lane&15));
    uint32_t bRowB = (uint32_t)(wn*32 + ((lane>>4)<<3) + (lane&7));
    int trow = lane>>2, tcol = (lane&3)*2;

    for(int t=blockIdx.x; t<ntiles; t+=gridDim.x){
        int m0=(t/ntn)<<7, n0=(t%ntn)<<7;
        float acc[4][4][4] = {};
#define LOADC(c) do{ \
    uint32_t base_=sb+((c)%3)*STG; int k0_=(c)*64; \
    _Pragma("unroll") \
    for(int j=0;j<4;j++){ \
        int idx=tid+j*256; int row=idx>>3, seg=idx&7; \
        uint32_t so=row*144+seg*16; \
        CP16(base_+so,        A +(size_t)(m0+row)*K+k0_+seg*8); \
        CP16(base_+ABYTES+so, Bh+(size_t)(n0+row)*K+k0_+seg*8); \
    } }while(0)
        LOADC(0); CP_COMMIT();
        LOADC(1); CP_COMMIT();
        for(int c=0;c<nch;c++){
            if(c+1<nch) CP_WAIT1(); else CP_WAIT0();
            __syncthreads();
            if(c+2<nch){ LOADC(c+2); CP_COMMIT(); }
            uint32_t base = sb + (c%3)*STG;
#pragma unroll
            for(int ks=0;ks<4;ks++){
                uint32_t abyte = ks*32 + ((lane>>4)<<4);
                uint32_t bbyte = ks*32 + (((lane>>3)&1)<<4);
                uint32_t bh_[2][4];
#pragma unroll
                for(int p=0;p<2;p++){
                    uint32_t bd = base + ABYTES + (bRowB + p*16)*144 + bbyte;
                    LDSM4(bh_[p], bd);
                }
#pragma unroll
                for(int mt=0;mt<4;mt++){
                    uint32_t af[4];
                    uint32_t ad = base + (aRowB + mt*16)*144 + abyte;
                    LDSM4(af, ad);
#pragma unroll
                    for(int nt=0;nt<4;nt++){
                        int p=nt>>1, s=(nt&1)*2;
                        MMA(acc[mt][nt], af, bh_[p][s], bh_[p][s+1]);
                    }
                }
            }
        }
        __syncthreads();

        int cb = n0 + wn*32;
        if(mode==7){
            int which = n0/768;
            const float* bp = (which==0)?bias:((which==1)?bias2:bias3);
#pragma unroll
            for(int mt=0;mt<4;mt++){
#pragma unroll
                for(int half=0;half<2;half++){
                    int r = m0 + wm*64 + mt*16 + trow + half*8;
#pragma unroll
                    for(int nt=0;nt<4;nt++){
                        int coll = cb + nt*8 + tcol - which*768;
                        float x0 = acc[mt][nt][half*2+0] + bp[coll];
                        float x1 = acc[mt][nt][half*2+1] + bp[coll+1];
                        if(which==0){
                            *(uint32_t*)(Ch + (size_t)r*Hh + coll) = packh2(x0,x1);
                        } else if(which==1){
                            *(uint32_t*)(C2h + (size_t)r*Hh + coll) = packh2(x0,x1);
                        } else {
                            int bi=r>>9, tok=r&511, hh=coll>>6, d=coll&63;
                            size_t b2 = (((size_t)bi*NHh + hh)*64 + d)*Ss + tok;
                            C3h[b2]    = __float2half_rn(x0);
                            C3h[b2+Ss] = __float2half_rn(x1);
                        }
                    }
                }
            }
        } else {
#pragma unroll
            for(int mt=0;mt<4;mt++){
#pragma unroll
                for(int half=0;half<2;half++){
                    int r = m0 + wm*64 + mt*16 + trow + half*8;
#pragma unroll
                    for(int nt=0;nt<4;nt++){
                        int col = cb + nt*8 + tcol;
                        float x0 = acc[mt][nt][half*2+0] + bias[col];
                        float x1 = acc[mt][nt][half*2+1] + bias[col+1];
                        x0 = 0.5f*x0*(1.f+erff(x0*0.70710678118654752f));
                        x1 = 0.5f*x1*(1.f+erff(x1*0.70710678118654752f));
                        *(uint32_t*)(Ch + (size_t)r*N + col) = packh2(x0,x1);
                    }
                }
            }
        }
    }
}

// ---- fp16 persistent GEMM, CTA 128x64 (O-proj / Wd; N=768; f32 out) ----
// 8 warps = 4m x 2n, warp tile 32x32. Less tail waste on the serial chain.
#define B64BYTES 9216
#define STG64 (ABYTES+B64BYTES)        // 27648
#define SMEM64 (3*STG64)               // 82944
__global__ void __launch_bounds__(256,2) mma_gemm64(
    const __half* __restrict__ A, const __half* __restrict__ Bh,
    const float* __restrict__ bias, float* __restrict__ C,
    int M, int N, int K)
{
    extern __shared__ __align__(128) char smem[];
    uint32_t sb = smem_u32(smem);
    int tid=threadIdx.x, lane=tid&31, wid=tid>>5;
    int nch=K>>6;
    int wm=wid>>1, wn=wid&1;          // wm 0..3 (32 rows), wn 0..1 (32 cols)
    int ntn=N>>6, ntiles=(M>>7)*ntn;
    uint32_t aRowB = (uint32_t)(wm*32 + (lane&15));
    uint32_t bRowB = (uint32_t)(wn*32 + ((lane>>4)<<3) + (lane&7));
    int trow = lane>>2, tcol = (lane&3)*2;

    for(int t=blockIdx.x; t<ntiles; t+=gridDim.x){
        int m0=(t/ntn)<<7, n0=(t%ntn)<<6;
        float acc[2][4][4] = {};
#define LOADC64(c) do{ \
    uint32_t base_=sb+((c)%3)*STG64; int k0_=(c)*64; \
    _Pragma("unroll") \
    for(int j=0;j<4;j++){ \
        int idx=tid+j*256; int row=idx>>3, seg=idx&7; \
        CP16(base_+row*144+seg*16, A +(size_t)(m0+row)*K+k0_+seg*8); \
    } \
    _Pragma("unroll") \
    for(int j=0;j<2;j++){ \
        int idx=tid+j*256; int row=idx>>3, seg=idx&7; \
        CP16(base_+ABYTES+row*144+seg*16, Bh+(size_t)(n0+row)*K+k0_+seg*8); \
    } }while(0)
        LOADC64(0); CP_COMMIT();
        LOADC64(1); CP_COMMIT();
        for(int c=0;c<nch;c++){
            if(c+1<nch) CP_WAIT1(); else CP_WAIT0();
            __syncthreads();
            if(c+2<nch){ LOADC64(c+2); CP_COMMIT(); }
            uint32_t base = sb + (c%3)*STG64;
#pragma unroll
            for(int ks=0;ks<4;ks++){
                uint32_t abyte = ks*32 + ((lane>>4)<<4);
                uint32_t bbyte = ks*32 + (((lane>>3)&1)<<4);
                uint32_t bh_[2][4];
#pragma unroll
                for(int p=0;p<2;p++){
                    uint32_t bd = base + ABYTES + (bRowB + p*16)*144 + bbyte;
                    LDSM4(bh_[p], bd);
                }
#pragma unroll
                for(int mt=0;mt<2;mt++){
                    uint32_t af[4];
                    uint32_t ad = base + (aRowB + mt*16)*144 + abyte;
                    LDSM4(af, ad);
#pragma unroll
                    for(int nt=0;nt<4;nt++){
                        int p=nt>>1, s=(nt&1)*2;
                        MMA(acc[mt][nt], af, bh_[p][s], bh_[p][s+1]);
                    }
                }
            }
        }
        __syncthreads();

        int cb = n0 + wn*32;
#pragma unroll
        for(int mt=0;mt<2;mt++){
#pragma unroll
            for(int half=0;half<2;half++){
                int r = m0 + wm*32 + mt*16 + trow + half*8;
#pragma unroll
                for(int nt=0;nt<4;nt++){
                    int col = cb + nt*8 + tcol;
                    float2 o;
                    o.x = acc[mt][nt][half*2+0] + bias[col];
                    o.y = acc[mt][nt][half*2+1] + bias[col+1];
                    *(float2*)(C + (size_t)r*N + col) = o;
                }
            }
        }
    }
}

// ---- fused flash attention: 128 q x 512 k x d64, all fp16, 256 threads ----
#define FSMEM 55808
__global__ void __launch_bounds__(256) flash_kernel(
    const __half* __restrict__ qh, const __half* __restrict__ kh,
    const __half* __restrict__ vth,
    const float* __restrict__ mask, __half* __restrict__ ctx)
{
    extern __shared__ __align__(128) char sm[];
    uint32_t sb = smem_u32(sm);
    int tid=threadIdx.x, lane=tid&31, wid=tid>>5;
    int q0=blockIdx.x*128, bh=blockIdx.y, b=bh/NHh, h=bh%NHh;
    size_t qb = ((size_t)(b*Ss+q0))*Hh + h*64;
    for(int i=tid;i<1024;i+=256){
        int r=i>>3, sg=i&7;
        CP16(sb + r*144 + sg*16, qh + qb + (size_t)r*Hh + sg*8);
    }
    CP_COMMIT();
#define KVBUF(s) (sb + 18432u + (s)*18432u)
#define LOADKV(kt,s) do{ \
    size_t kb_ = ((size_t)(b*Ss + (kt)*64))*Hh + h*64; \
    size_t vb_ = ((size_t)bh*64)*Ss + (kt)*64; \
    uint32_t dst_=KVBUF(s); \
    for(int i_=tid;i_<512;i_+=256){ \
        int r_=i_>>3, sg_=i_&7; \
        CP16(dst_ + r_*144 + sg_*16,        kh  + kb_ + (size_t)r_*Hh + sg_*8); \
        CP16(dst_ + 9216 + r_*144 + sg_*16, vth + vb_ + (size_t)r_*Ss + sg_*8); \
    } \
    if(tid<64){ float mv_=mask[b*Ss+(kt)*64+tid]; \
        ((float*)(sm + 55296 + (s)*256))[tid] = (1.f-mv_)*-10000.f; } \
    }while(0)
    LOADKV(0,0); CP_COMMIT();
    CP_WAIT1(); __syncthreads();
    uint32_t qf[4][4];
#pragma unroll
    for(int ks=0;ks<4;ks++){
        uint32_t ad = sb + (wid*16 + (lane&15))*144 + ks*32 + ((lane>>4)<<4);
        LDSM4(qf[ks], ad);
    }
    float m0=-1e30f, m1=-1e30f, l0=0.f, l1=0.f;
    float o[8][4] = {};
    int tc = (lane&3)*2;
    for(int kt=0;kt<8;kt++){
        int s=kt&1;
        if(kt<7){ LOADKV(kt+1, s^1); CP_COMMIT(); CP_WAIT1(); }
        else CP_WAIT0();
        __syncthreads();
        uint32_t kbuf=KVBUF(s), vbuf=KVBUF(s)+9216u;
        const float* extp = (const float*)(sm + 55296 + s*256);
        float sc[8][4] = {};
#pragma unroll
        for(int ks=0;ks<4;ks++){
#pragma unroll
            for(int j2=0;j2<4;j2++){
                uint32_t kf[4];
                uint32_t ad = kbuf + (j2*16 + (lane&7) + ((lane>>4)<<3))*144 + ks*32 + (((lane>>3)&1)<<4);
                LDSM4(kf, ad);
                MMA(sc[2*j2],   qf[ks], kf[0], kf[1]);
                MMA(sc[2*j2+1], qf[ks], kf[2], kf[3]);
            }
        }
        float mt0=-1e30f, mt1=-1e30f;
#pragma unroll
        for(int j=0;j<8;j++){
            float e0 = extp[j*8+tc], e1 = extp[j*8+tc+1];
            sc[j][0]=sc[j][0]*0.125f+e0; sc[j][1]=sc[j][1]*0.125f+e1;
            sc[j][2]=sc[j][2]*0.125f+e0; sc[j][3]=sc[j][3]*0.125f+e1;
            mt0=fmaxf(mt0,fmaxf(sc[j][0],sc[j][1]));
            mt1=fmaxf(mt1,fmaxf(sc[j][2],sc[j][3]));
        }
        mt0=fmaxf(mt0,__shfl_xor_sync(0xffffffffu,mt0,1));
        mt0=fmaxf(mt0,__shfl_xor_sync(0xffffffffu,mt0,2));
        mt1=fmaxf(mt1,__shfl_xor_sync(0xffffffffu,mt1,1));
        mt1=fmaxf(mt1,__shfl_xor_sync(0xffffffffu,mt1,2));
        float mn0=fmaxf(m0,mt0), mn1=fmaxf(m1,mt1);
        float s0=__expf(m0-mn0), s1=__expf(m1-mn1);
        float rs0=0.f, rs1=0.f;
#pragma unroll
        for(int j=0;j<8;j++){
            sc[j][0]=__expf(sc[j][0]-mn0); sc[j][1]=__expf(sc[j][1]-mn0);
            sc[j][2]=__expf(sc[j][2]-mn1); sc[j][3]=__expf(sc[j][3]-mn1);
            rs0+=sc[j][0]+sc[j][1]; rs1+=sc[j][2]+sc[j][3];
            o[j][0]*=s0; o[j][1]*=s0; o[j][2]*=s1; o[j][3]*=s1;
        }
        rs0+=__shfl_xor_sync(0xffffffffu,rs0,1); rs0+=__shfl_xor_sync(0xffffffffu,rs0,2);
        rs1+=__shfl_xor_sync(0xffffffffu,rs1,1); rs1+=__shfl_xor_sync(0xffffffffu,rs1,2);
        l0=l0*s0+rs0; l1=l1*s1+rs1; m0=mn0; m1=mn1;
#pragma unroll
        for(int ks=0;ks<4;ks++){
            uint32_t pah[4];
#pragma unroll
            for(int jj=0;jj<2;jj++){
                int j=2*ks+jj;
                pah[jj*2+0]=packh2(sc[j][0],sc[j][1]);
                pah[jj*2+1]=packh2(sc[j][2],sc[j][3]);
            }
#pragma unroll
            for(int d2=0;d2<4;d2++){
                uint32_t vf[4];
                uint32_t ad = vbuf + (d2*16 + (lane&7) + ((lane>>4)<<3))*144 + ks*32 + (((lane>>3)&1)<<4);
                LDSM4(vf,ad);
                MMA(o[2*d2],   pah, vf[0], vf[1]);
                MMA(o[2*d2+1], pah, vf[2], vf[3]);
            }
        }
        __syncthreads();
    }
    float il0=1.f/l0, il1=1.f/l1;
    int row_lo = b*Ss + q0 + wid*16 + (lane>>2);
#pragma unroll
    for(int j=0;j<8;j++){
        int col = h*64 + j*8 + tc;
        *(uint32_t*)(ctx + (size_t)row_lo*Hh + col)     = packh2(o[j][0]*il0, o[j][1]*il0);
        *(uint32_t*)(ctx + (size_t)(row_lo+8)*Hh + col) = packh2(o[j][2]*il1, o[j][3]*il1);
    }
}

// ---- embedding + LN + noise (writes fp32 x AND fp16 stage) ----
__global__ void embed_kernel(const int* __restrict__ ids, const int* __restrict__ tt,
                             const float* __restrict__ imp, const float* __restrict__ noise,
                             const float* __restrict__ we, const float* __restrict__ pe,
                             const float* __restrict__ te, const float* __restrict__ g,
                             const float* __restrict__ bta){
    int row=blockIdx.x, tid=threadIdx.x;
    int s_=row%Ss, id=ids[row], t=tt[row];
    float v[3], sum=0.f, sum2=0.f;
#pragma unroll
    for(int j=0;j<3;j++){
        int c=tid+j*256;
        float e=we[(size_t)id*Hh+c]+pe[(size_t)s_*Hh+c]+te[(size_t)t*Hh+c];
        v[j]=e; sum+=e; sum2+=e*e;
    }
    __shared__ float r1[256], r2[256];
    r1[tid]=sum; r2[tid]=sum2; __syncthreads();
    for(int st=128;st>0;st>>=1){ if(tid<st){ r1[tid]+=r1[tid+st]; r2[tid]+=r2[tid+st]; } __syncthreads(); }
    float mean=r1[0]*(1.f/Hh), var=r2[0]*(1.f/Hh)-mean*mean;
    float rstd=rsqrtf(var+1e-12f);
    float im=imp[row], fac=(im!=0.f)?1.f:0.f, sig=1.f-im;
#pragma unroll
    for(int j=0;j<3;j++){
        int c=tid+j*256;
        float y=(v[j]-mean)*rstd*g[c]+bta[c];
        y=y*(1.f+fac*noise[(size_t)row*Hh+c]*sig);
        g_x[(size_t)row*Hh+c]=y;
        g_ah[(size_t)row*Hh+c]=__float2half_rn(y);
    }
}

// ---- residual add + LN, 192 threads x float4, shuffle reduce ----
__global__ void __launch_bounds__(192) add_ln_kernel(const float* __restrict__ t,
                              const float* __restrict__ g, const float* __restrict__ bta){
    int row=blockIdx.x, tid=threadIdx.x;
    int c=tid*4;
    size_t off=(size_t)row*Hh+c;
    float4 xv=*(const float4*)(g_x+off);
    float4 tv=*(const float4*)(t+off);
    float4 e; e.x=xv.x+tv.x; e.y=xv.y+tv.y; e.z=xv.z+tv.z; e.w=xv.w+tv.w;
    float sum=e.x+e.y+e.z+e.w;
    float sum2=e.x*e.x+e.y*e.y+e.z*e.z+e.w*e.w;
#pragma unroll
    for(int st=16;st>0;st>>=1){
        sum +=__shfl_xor_sync(0xffffffffu,sum ,st);
        sum2+=__shfl_xor_sync(0xffffffffu,sum2,st);
    }
    __shared__ float w1[6], w2[6];
    int wid=tid>>5, lane=tid&31;
    if(lane==0){ w1[wid]=sum; w2[wid]=sum2; }
    __syncthreads();
    float ts1=w1[0]+w1[1]+w1[2]+w1[3]+w1[4]+w1[5];
    float ts2=w2[0]+w2[1]+w2[2]+w2[3]+w2[4]+w2[5];
    float mean=ts1*(1.f/Hh), var=ts2*(1.f/Hh)-mean*mean;
    float rstd=rsqrtf(var+1e-12f);
    float4 gv=*(const float4*)(g+c);
    float4 bv=*(const float4*)(bta+c);
    float4 y;
    y.x=(e.x-mean)*rstd*gv.x+bv.x;
    y.y=(e.y-mean)*rstd*gv.y+bv.y;
    y.z=(e.z-mean)*rstd*gv.z+bv.z;
    y.w=(e.w-mean)*rstd*gv.w+bv.w;
    *(float4*)(g_x+off)=y;
    uint2 hx;
    hx.x=packh2(y.x,y.y); hx.y=packh2(y.z,y.w);
    *(uint2*)(g_ah+off)=hx;
}

__global__ void pooler_kernel(const float* __restrict__ w, const float* __restrict__ bias,
                              float* __restrict__ out){
    int b=blockIdx.y, j=blockIdx.x*256+threadIdx.x;
    const float* xr=g_x+(size_t)b*Ss*Hh;
    float s=bias[j];
    for(int i=0;i<Hh;i++) s+=xr[i]*w[(size_t)i*Hh+j];
    out[(size_t)b*Hh+j]=tanhf(s);
}
__global__ void copy_x_kernel(float* __restrict__ out){
    size_t i=(size_t)blockIdx.x*256+threadIdx.x;
    out[i]=g_x[i];
}

extern "C" void kernel_launch(void* const* d_in, const int* in_sizes, int n_in,
                              void* d_out, int out_size){
    const int* ids=(const int*)d_in[0];  const int* tt=(const int*)d_in[1];
    const float* mask=(const float*)d_in[2]; const float* imp=(const float*)d_in[3];
    const float* noi=(const float*)d_in[4];
    const float* we=(const float*)d_in[5]; const float* pe=(const float*)d_in[6];
    const float* te=(const float*)d_in[7];
    const float* elng=(const float*)d_in[8]; const float* elnb=(const float*)d_in[9];
    const float* Wq=(const float*)d_in[10]; const float* bq=(const float*)d_in[11];
    const float* Wk=(const float*)d_in[12]; const float* bk=(const float*)d_in[13];
    const float* Wv=(const float*)d_in[14]; const float* bv=(const float*)d_in[15];
    const float* Wo=(const float*)d_in[16]; const float* bo=(const float*)d_in[17];
    const float* g1=(const float*)d_in[18]; const float* b1=(const float*)d_in[19];
    const float* Wi=(const float*)d_in[20]; const float* bi=(const float*)d_in[21];
    const float* Wd=(const float*)d_in[22]; const float* bd=(const float*)d_in[23];
    const float* g2=(const float*)d_in[24]; const float* b2=(const float*)d_in[25];
    const float* pw=(const float*)d_in[26]; const float* pb=(const float*)d_in[27];
    float* out=(float*)d_out;

    float *pt;
    __half *pah,*pch,*pqh,*pkh,*pvth,*pfh,*pwh;
    cudaGetSymbolAddress((void**)&pt,g_t);
    cudaGetSymbolAddress((void**)&pah,g_ah); cudaGetSymbolAddress((void**)&pch,g_ch);
    cudaGetSymbolAddress((void**)&pqh,g_qh);
    cudaGetSymbolAddress((void**)&pkh,g_kh);
    cudaGetSymbolAddress((void**)&pvth,g_vth);
    cudaGetSymbolAddress((void**)&pfh,g_fh);
    cudaGetSymbolAddress((void**)&pwh,g_wh);

    cudaFuncSetAttribute(mma_gemm, cudaFuncAttributeMaxDynamicSharedMemorySize, SMEMSZ);
    cudaFuncSetAttribute(mma_gemm64, cudaFuncAttributeMaxDynamicSharedMemorySize, SMEM64);
    cudaFuncSetAttribute(flash_kernel, cudaFuncAttributeMaxDynamicSharedMemorySize, FSMEM);

    dim3 gFl(Ss/128, Bb*NHh);

    embed_kernel<<<Mm,256>>>(ids,tt,imp,noi,we,pe,te,elng,elnb);
    w_stage_all<<<82944,256>>>(Wq,Wk,Wv,Wo,Wi,Wd, pwh);

    for(int l=0;l<Ll;l++){
        size_t wl=(size_t)l*WLSTR, oH=(size_t)l*Hh, oF=(size_t)l*FFf;
        mma_gemm<<<GRIDP,256,SMEMSZ>>>(pah, pwh+wl+OQW,
                                       bq+oH, bk+oH, bv+oH,
                                       pqh, pkh, pvth, Mm, 2304, Hh, 7);
        flash_kernel<<<gFl,256,FSMEM>>>(pqh, pkh, pvth, mask, pch);
        mma_gemm64<<<GRIDP,256,SMEM64>>>(pch, pwh+wl+OOW, bo+oH, pt, Mm, Hh, Hh);
        add_ln_kernel<<<Mm,192>>>(pt, g1+oH, b1+oH);
        mma_gemm<<<GRIDP,256,SMEMSZ>>>(pah, pwh+wl+OIW,
                                       bi+oF, 0,0, pfh, 0,0, Mm, FFf, Hh, 3);
        mma_gemm64<<<GRIDP,256,SMEM64>>>(pfh, pwh+wl+ODW, bd+oH, pt, Mm, Hh, FFf);
        add_ln_kernel<<<Mm,192>>>(pt, g2+oH, b2+oH);
    }

    copy_x_kernel<<<(Mm*Hh)/256,256>>>(out);
    pooler_kernel<<<dim3(Hh/256,Bb),256>>>(pw, pb, out+(size_t)Mm*Hh);
}

// round 15
// speedup vs baseline: 1.0938x; 1.0938x over previous
#include <cuda_runtime.h>
#include <cuda_fp16.h>
#include <math.h>
#include <stdint.h>

#define Bb 16
#define Ss 512
#define Hh 768
#define Ll 12
#define NHh 12
#define FFf 3072
#define Mm (Bb*Ss)
#define GRIDP 296

__device__ float g_x [(size_t)Mm*Hh];
__device__ float g_t [(size_t)Mm*Hh];
__device__ __align__(16) __half g_ah [(size_t)Mm*Hh];
__device__ __align__(16) __half g_ch [(size_t)Mm*Hh];
__device__ __align__(16) __half g_qh [(size_t)Mm*Hh];
__device__ __align__(16) __half g_kh [(size_t)Mm*Hh];
__device__ __align__(16) __half g_vth[(size_t)Mm*Hh];
__device__ __align__(16) __half g_fh [(size_t)Mm*FFf];
#define WLSTR 7077888ULL
__device__ __align__(16) __half g_wh[WLSTR*Ll];
#define OQW 0ULL
#define OKW 589824ULL
#define OVW 1179648ULL
#define OOW 1769472ULL
#define OIW 2359296ULL
#define ODW 4718592ULL

__device__ __forceinline__ uint32_t smem_u32(const void* p){
    uint32_t a; asm("{ .reg .u64 t; cvta.to.shared.u64 t, %1; cvt.u32.u64 %0, t; }":"=r"(a):"l"(p)); return a;
}
#define CP16(dst,src) asm volatile("cp.async.cg.shared.global [%0], [%1], 16;"::"r"(dst),"l"(src))
#define CP_COMMIT()   asm volatile("cp.async.commit_group;")
#define CP_WAIT1()    asm volatile("cp.async.wait_group 1;")
#define CP_WAIT0()    asm volatile("cp.async.wait_group 0;")
#define LDSM4(R,a) asm volatile("ldmatrix.sync.aligned.m8n8.x4.shared.b16 {%0,%1,%2,%3}, [%4];" \
    : "=r"((R)[0]),"=r"((R)[1]),"=r"((R)[2]),"=r"((R)[3]) : "r"(a))
#define MMA(C,A,b0,b1) asm volatile( \
    "mma.sync.aligned.m16n8k16.row.col.f32.f16.f16.f32 {%0,%1,%2,%3}, {%4,%5,%6,%7}, {%8,%9}, {%0,%1,%2,%3};" \
    : "+f"((C)[0]),"+f"((C)[1]),"+f"((C)[2]),"+f"((C)[3]) \
    : "r"((A)[0]),"r"((A)[1]),"r"((A)[2]),"r"((A)[3]), "r"(b0),"r"(b1))

__device__ __forceinline__ uint32_t packh2(float a, float b){
    __half2 h = __floats2half2_rn(a,b);
    return *(uint32_t*)&h;
}

// ---- all-weights staging: W[K,N] fp32 -> Wt[N,K] fp16, ONE launch ----
__global__ void w_stage_all(const float* __restrict__ Wq, const float* __restrict__ Wk,
                            const float* __restrict__ Wv, const float* __restrict__ Wo,
                            const float* __restrict__ Wi, const float* __restrict__ Wd,
                            __half* __restrict__ th){
    __shared__ float tile[32][33];
    int bi=blockIdx.x;
    const float* W; size_t ob; int N,K,n0,k0;
    if(bi<27648){
        int w=bi/6912, local=bi%6912;
        W = (w==0)?Wq:(w==1)?Wk:(w==2)?Wv:Wo;
        ob = (size_t)w*589824ULL;
        N=768; K=768;
        int l=local/576, rem=local%576;
        W += (size_t)l*589824ULL; ob += (size_t)l*WLSTR;
        n0=(rem%24)*32; k0=(rem/24)*32;
    } else if(bi<55296){
        int local=bi-27648;
        W=Wi; ob=OIW; N=3072; K=768;
        int l=local/2304, rem=local%2304;
        W += (size_t)l*2359296ULL; ob += (size_t)l*WLSTR;
        n0=(rem%96)*32; k0=(rem/96)*32;
    } else {
        int local=bi-55296;
        W=Wd; ob=ODW; N=768; K=3072;
        int l=local/2304, rem=local%2304;
        W += (size_t)l*2359296ULL; ob += (size_t)l*WLSTR;
        n0=(rem%24)*32; k0=(rem/24)*32;
    }
    int tx=threadIdx.x&31, ty=threadIdx.x>>5;
    for(int i=ty;i<32;i+=8) tile[i][tx]=W[(size_t)(k0+i)*N+n0+tx];
    __syncthreads();
    for(int i=ty;i<32;i+=8){
        size_t o=ob+(size_t)(n0+i)*K+k0+tx;
        th[o]=__float2half_rn(tile[tx][i]);
    }
}

// ---- fp16 persistent tensor-core GEMM, CTA 128x128 ----
// mode: 0=f32 out, 3=gelu+fp16 hi, 7=fused QKV epilogue
#define ABYTES 18432
#define STG (2*ABYTES)
#define SMEMSZ (3*STG)
__global__ void __launch_bounds__(256,2) mma_gemm(
    const __half* __restrict__ A, const __half* __restrict__ Bh,
    const float* __restrict__ bias, const float* __restrict__ bias2, const float* __restrict__ bias3,
    float* __restrict__ C, __half* __restrict__ Ch,
    __half* __restrict__ C2h, __half* __restrict__ C3h,
    int M, int N, int K, int mode)
{
    extern __shared__ __align__(128) char smem[];
    uint32_t sb = smem_u32(smem);
    int tid=threadIdx.x, lane=tid&31, wid=tid>>5;
    int nch=K>>6;
    int wm=wid>>2, wn=wid&3;
    int ntn=N>>7, ntiles=(M>>7)*ntn;
    uint32_t aRowB = (uint32_t)(wm*64 + (lane&15));
    uint32_t bRowB = (uint32_t)(wn*32 + ((lane>>4)<<3) + (lane&7));
    int trow = lane>>2, tcol = (lane&3)*2;

    for(int t=blockIdx.x; t<ntiles; t+=gridDim.x){
        int m0=(t/ntn)<<7, n0=(t%ntn)<<7;
        float acc[4][4][4] = {};
#define LOADC(c) do{ \
    uint32_t base_=sb+((c)%3)*STG; int k0_=(c)*64; \
    _Pragma("unroll") \
    for(int j=0;j<4;j++){ \
        int idx=tid+j*256; int row=idx>>3, seg=idx&7; \
        uint32_t so=row*144+seg*16; \
        CP16(base_+so,        A +(size_t)(m0+row)*K+k0_+seg*8); \
        CP16(base_+ABYTES+so, Bh+(size_t)(n0+row)*K+k0_+seg*8); \
    } }while(0)
        LOADC(0); CP_COMMIT();
        LOADC(1); CP_COMMIT();
        for(int c=0;c<nch;c++){
            if(c+1<nch) CP_WAIT1(); else CP_WAIT0();
            __syncthreads();
            if(c+2<nch){ LOADC(c+2); CP_COMMIT(); }
            uint32_t base = sb + (c%3)*STG;
#pragma unroll
            for(int ks=0;ks<4;ks++){
                uint32_t abyte = ks*32 + ((lane>>4)<<4);
                uint32_t bbyte = ks*32 + (((lane>>3)&1)<<4);
                uint32_t bh_[2][4];
#pragma unroll
                for(int p=0;p<2;p++){
                    uint32_t bd = base + ABYTES + (bRowB + p*16)*144 + bbyte;
                    LDSM4(bh_[p], bd);
                }
#pragma unroll
                for(int mt=0;mt<4;mt++){
                    uint32_t af[4];
                    uint32_t ad = base + (aRowB + mt*16)*144 + abyte;
                    LDSM4(af, ad);
#pragma unroll
                    for(int nt=0;nt<4;nt++){
                        int p=nt>>1, s=(nt&1)*2;
                        MMA(acc[mt][nt], af, bh_[p][s], bh_[p][s+1]);
                    }
                }
            }
        }
        __syncthreads();

        int cb = n0 + wn*32;
        if(mode==7){
            int which = n0/768;
            const float* bp = (which==0)?bias:((which==1)?bias2:bias3);
#pragma unroll
            for(int mt=0;mt<4;mt++){
#pragma unroll
                for(int half=0;half<2;half++){
                    int r = m0 + wm*64 + mt*16 + trow + half*8;
#pragma unroll
                    for(int nt=0;nt<4;nt++){
                        int coll = cb + nt*8 + tcol - which*768;
                        float x0 = acc[mt][nt][half*2+0] + bp[coll];
                        float x1 = acc[mt][nt][half*2+1] + bp[coll+1];
                        if(which==0){
                            *(uint32_t*)(Ch + (size_t)r*Hh + coll) = packh2(x0,x1);
                        } else if(which==1){
                            *(uint32_t*)(C2h + (size_t)r*Hh + coll) = packh2(x0,x1);
                        } else {
                            int bi=r>>9, tok=r&511, hh=coll>>6, d=coll&63;
                            size_t b2 = (((size_t)bi*NHh + hh)*64 + d)*Ss + tok;
                            C3h[b2]    = __float2half_rn(x0);
                            C3h[b2+Ss] = __float2half_rn(x1);
                        }
                    }
                }
            }
        } else {
#pragma unroll
            for(int mt=0;mt<4;mt++){
#pragma unroll
                for(int half=0;half<2;half++){
                    int r = m0 + wm*64 + mt*16 + trow + half*8;
#pragma unroll
                    for(int nt=0;nt<4;nt++){
                        int col = cb + nt*8 + tcol;
                        float x0 = acc[mt][nt][half*2+0] + bias[col];
                        float x1 = acc[mt][nt][half*2+1] + bias[col+1];
                        if(mode==3){
                            x0 = 0.5f*x0*(1.f+erff(x0*0.70710678118654752f));
                            x1 = 0.5f*x1*(1.f+erff(x1*0.70710678118654752f));
                            *(uint32_t*)(Ch + (size_t)r*N + col) = packh2(x0,x1);
                        } else {
                            float2 o; o.x=x0; o.y=x1;
                            *(float2*)(C + (size_t)r*N + col) = o;
                        }
                    }
                }
            }
        }
    }
}

// ---- fused flash attention: 128 q x 512 k x d64, all fp16, 256 threads ----
#define FSMEM 55808
__global__ void __launch_bounds__(256) flash_kernel(
    const __half* __restrict__ qh, const __half* __restrict__ kh,
    const __half* __restrict__ vth,
    const float* __restrict__ mask, __half* __restrict__ ctx)
{
    extern __shared__ __align__(128) char sm[];
    uint32_t sb = smem_u32(sm);
    int tid=threadIdx.x, lane=tid&31, wid=tid>>5;
    int q0=blockIdx.x*128, bh=blockIdx.y, b=bh/NHh, h=bh%NHh;
    size_t qb = ((size_t)(b*Ss+q0))*Hh + h*64;
    for(int i=tid;i<1024;i+=256){
        int r=i>>3, sg=i&7;
        CP16(sb + r*144 + sg*16, qh + qb + (size_t)r*Hh + sg*8);
    }
    CP_COMMIT();
#define KVBUF(s) (sb + 18432u + (s)*18432u)
#define LOADKV(kt,s) do{ \
    size_t kb_ = ((size_t)(b*Ss + (kt)*64))*Hh + h*64; \
    size_t vb_ = ((size_t)bh*64)*Ss + (kt)*64; \
    uint32_t dst_=KVBUF(s); \
    for(int i_=tid;i_<512;i_+=256){ \
        int r_=i_>>3, sg_=i_&7; \
        CP16(dst_ + r_*144 + sg_*16,        kh  + kb_ + (size_t)r_*Hh + sg_*8); \
        CP16(dst_ + 9216 + r_*144 + sg_*16, vth + vb_ + (size_t)r_*Ss + sg_*8); \
    } \
    if(tid<64){ float mv_=mask[b*Ss+(kt)*64+tid]; \
        ((float*)(sm + 55296 + (s)*256))[tid] = (1.f-mv_)*-10000.f; } \
    }while(0)
    LOADKV(0,0); CP_COMMIT();
    CP_WAIT1(); __syncthreads();
    uint32_t qf[4][4];
#pragma unroll
    for(int ks=0;ks<4;ks++){
        uint32_t ad = sb + (wid*16 + (lane&15))*144 + ks*32 + ((lane>>4)<<4);
        LDSM4(qf[ks], ad);
    }
    float m0=-1e30f, m1=-1e30f, l0=0.f, l1=0.f;
    float o[8][4] = {};
    int tc = (lane&3)*2;
    for(int kt=0;kt<8;kt++){
        int s=kt&1;
        if(kt<7){ LOADKV(kt+1, s^1); CP_COMMIT(); CP_WAIT1(); }
        else CP_WAIT0();
        __syncthreads();
        uint32_t kbuf=KVBUF(s), vbuf=KVBUF(s)+9216u;
        const float* extp = (const float*)(sm + 55296 + s*256);
        float sc[8][4] = {};
#pragma unroll
        for(int ks=0;ks<4;ks++){
#pragma unroll
            for(int j2=0;j2<4;j2++){
                uint32_t kf[4];
                uint32_t ad = kbuf + (j2*16 + (lane&7) + ((lane>>4)<<3))*144 + ks*32 + (((lane>>3)&1)<<4);
                LDSM4(kf, ad);
                MMA(sc[2*j2],   qf[ks], kf[0], kf[1]);
                MMA(sc[2*j2+1], qf[ks], kf[2], kf[3]);
            }
        }
        float mt0=-1e30f, mt1=-1e30f;
#pragma unroll
        for(int j=0;j<8;j++){
            float e0 = extp[j*8+tc], e1 = extp[j*8+tc+1];
            sc[j][0]=sc[j][0]*0.125f+e0; sc[j][1]=sc[j][1]*0.125f+e1;
            sc[j][2]=sc[j][2]*0.125f+e0; sc[j][3]=sc[j][3]*0.125f+e1;
            mt0=fmaxf(mt0,fmaxf(sc[j][0],sc[j][1]));
            mt1=fmaxf(mt1,fmaxf(sc[j][2],sc[j][3]));
        }
        mt0=fmaxf(mt0,__shfl_xor_sync(0xffffffffu,mt0,1));
        mt0=fmaxf(mt0,__shfl_xor_sync(0xffffffffu,mt0,2));
        mt1=fmaxf(mt1,__shfl_xor_sync(0xffffffffu,mt1,1));
        mt1=fmaxf(mt1,__shfl_xor_sync(0xffffffffu,mt1,2));
        float mn0=fmaxf(m0,mt0), mn1=fmaxf(m1,mt1);
        float s0=__expf(m0-mn0), s1=__expf(m1-mn1);
        float rs0=0.f, rs1=0.f;
#pragma unroll
        for(int j=0;j<8;j++){
            sc[j][0]=__expf(sc[j][0]-mn0); sc[j][1]=__expf(sc[j][1]-mn0);
            sc[j][2]=__expf(sc[j][2]-mn1); sc[j][3]=__expf(sc[j][3]-mn1);
            rs0+=sc[j][0]+sc[j][1]; rs1+=sc[j][2]+sc[j][3];
            o[j][0]*=s0; o[j][1]*=s0; o[j][2]*=s1; o[j][3]*=s1;
        }
        rs0+=__shfl_xor_sync(0xffffffffu,rs0,1); rs0+=__shfl_xor_sync(0xffffffffu,rs0,2);
        rs1+=__shfl_xor_sync(0xffffffffu,rs1,1); rs1+=__shfl_xor_sync(0xffffffffu,rs1,2);
        l0=l0*s0+rs0; l1=l1*s1+rs1; m0=mn0; m1=mn1;
#pragma unroll
        for(int ks=0;ks<4;ks++){
            uint32_t pah[4];
#pragma unroll
            for(int jj=0;jj<2;jj++){
                int j=2*ks+jj;
                pah[jj*2+0]=packh2(sc[j][0],sc[j][1]);
                pah[jj*2+1]=packh2(sc[j][2],sc[j][3]);
            }
#pragma unroll
            for(int d2=0;d2<4;d2++){
                uint32_t vf[4];
                uint32_t ad = vbuf + (d2*16 + (lane&7) + ((lane>>4)<<3))*144 + ks*32 + (((lane>>3)&1)<<4);
                LDSM4(vf,ad);
                MMA(o[2*d2],   pah, vf[0], vf[1]);
                MMA(o[2*d2+1], pah, vf[2], vf[3]);
            }
        }
        __syncthreads();
    }
    float il0=1.f/l0, il1=1.f/l1;
    int row_lo = b*Ss + q0 + wid*16 + (lane>>2);
#pragma unroll
    for(int j=0;j<8;j++){
        int col = h*64 + j*8 + tc;
        *(uint32_t*)(ctx + (size_t)row_lo*Hh + col)     = packh2(o[j][0]*il0, o[j][1]*il0);
        *(uint32_t*)(ctx + (size_t)(row_lo+8)*Hh + col) = packh2(o[j][2]*il1, o[j][3]*il1);
    }
}

// ---- embedding + LN + noise (writes fp32 x AND fp16 stage) ----
__global__ void embed_kernel(const int* __restrict__ ids, const int* __restrict__ tt,
                             const float* __restrict__ imp, const float* __restrict__ noise,
                             const float* __restrict__ we, const float* __restrict__ pe,
                             const float* __restrict__ te, const float* __restrict__ g,
                             const float* __restrict__ bta){
    int row=blockIdx.x, tid=threadIdx.x;
    int s_=row%Ss, id=ids[row], t=tt[row];
    float v[3], sum=0.f, sum2=0.f;
#pragma unroll
    for(int j=0;j<3;j++){
        int c=tid+j*256;
        float e=we[(size_t)id*Hh+c]+pe[(size_t)s_*Hh+c]+te[(size_t)t*Hh+c];
        v[j]=e; sum+=e; sum2+=e*e;
    }
    __shared__ float r1[256], r2[256];
    r1[tid]=sum; r2[tid]=sum2; __syncthreads();
    for(int st=128;st>0;st>>=1){ if(tid<st){ r1[tid]+=r1[tid+st]; r2[tid]+=r2[tid+st]; } __syncthreads(); }
    float mean=r1[0]*(1.f/Hh), var=r2[0]*(1.f/Hh)-mean*mean;
    float rstd=rsqrtf(var+1e-12f);
    float im=imp[row], fac=(im!=0.f)?1.f:0.f, sig=1.f-im;
#pragma unroll
    for(int j=0;j<3;j++){
        int c=tid+j*256;
        float y=(v[j]-mean)*rstd*g[c]+bta[c];
        y=y*(1.f+fac*noise[(size_t)row*Hh+c]*sig);
        g_x[(size_t)row*Hh+c]=y;
        g_ah[(size_t)row*Hh+c]=__float2half_rn(y);
    }
}

// ---- residual add + LN, 192 threads x float4, shuffle reduce ----
__global__ void __launch_bounds__(192) add_ln_kernel(const float* __restrict__ t,
                              const float* __restrict__ g, const float* __restrict__ bta){
    int row=blockIdx.x, tid=threadIdx.x;
    int c=tid*4;
    size_t off=(size_t)row*Hh+c;
    float4 xv=*(const float4*)(g_x+off);
    float4 tv=*(const float4*)(t+off);
    float4 e; e.x=xv.x+tv.x; e.y=xv.y+tv.y; e.z=xv.z+tv.z; e.w=xv.w+tv.w;
    float sum=e.x+e.y+e.z+e.w;
    float sum2=e.x*e.x+e.y*e.y+e.z*e.z+e.w*e.w;
#pragma unroll
    for(int st=16;st>0;st>>=1){
        sum +=__shfl_xor_sync(0xffffffffu,sum ,st);
        sum2+=__shfl_xor_sync(0xffffffffu,sum2,st);
    }
    __shared__ float w1[6], w2[6];
    int wid=tid>>5, lane=tid&31;
    if(lane==0){ w1[wid]=sum; w2[wid]=sum2; }
    __syncthreads();
    float ts1=w1[0]+w1[1]+w1[2]+w1[3]+w1[4]+w1[5];
    float ts2=w2[0]+w2[1]+w2[2]+w2[3]+w2[4]+w2[5];
    float mean=ts1*(1.f/Hh), var=ts2*(1.f/Hh)-mean*mean;
    float rstd=rsqrtf(var+1e-12f);
    float4 gv=*(const float4*)(g+c);
    float4 bv=*(const float4*)(bta+c);
    float4 y;
    y.x=(e.x-mean)*rstd*gv.x+bv.x;
    y.y=(e.y-mean)*rstd*gv.y+bv.y;
    y.z=(e.z-mean)*rstd*gv.z+bv.z;
    y.w=(e.w-mean)*rstd*gv.w+bv.w;
    *(float4*)(g_x+off)=y;
    uint2 hx;
    hx.x=packh2(y.x,y.y); hx.y=packh2(y.z,y.w);
    *(uint2*)(g_ah+off)=hx;
}

__global__ void pooler_kernel(const float* __restrict__ w, const float* __restrict__ bias,
                              float* __restrict__ out){
    int b=blockIdx.y, j=blockIdx.x*256+threadIdx.x;
    const float* xr=g_x+(size_t)b*Ss*Hh;
    float s=bias[j];
    for(int i=0;i<Hh;i++) s+=xr[i]*w[(size_t)i*Hh+j];
    out[(size_t)b*Hh+j]=tanhf(s);
}
__global__ void copy_x_kernel(float* __restrict__ out){
    size_t i=(size_t)blockIdx.x*256+threadIdx.x;
    out[i]=g_x[i];
}

extern "C" void kernel_launch(void* const* d_in, const int* in_sizes, int n_in,
                              void* d_out, int out_size){
    const int* ids=(const int*)d_in[0];  const int* tt=(const int*)d_in[1];
    const float* mask=(const float*)d_in[2]; const float* imp=(const float*)d_in[3];
    const float* noi=(const float*)d_in[4];
    const float* we=(const float*)d_in[5]; const float* pe=(const float*)d_in[6];
    const float* te=(const float*)d_in[7];
    const float* elng=(const float*)d_in[8]; const float* elnb=(const float*)d_in[9];
    const float* Wq=(const float*)d_in[10]; const float* bq=(const float*)d_in[11];
    const float* Wk=(const float*)d_in[12]; const float* bk=(const float*)d_in[13];
    const float* Wv=(const float*)d_in[14]; const float* bv=(const float*)d_in[15];
    const float* Wo=(const float*)d_in[16]; const float* bo=(const float*)d_in[17];
    const float* g1=(const float*)d_in[18]; const float* b1=(const float*)d_in[19];
    const float* Wi=(const float*)d_in[20]; const float* bi=(const float*)d_in[21];
    const float* Wd=(const float*)d_in[22]; const float* bd=(const float*)d_in[23];
    const float* g2=(const float*)d_in[24]; const float* b2=(const float*)d_in[25];
    const float* pw=(const float*)d_in[26]; const float* pb=(const float*)d_in[27];
    float* out=(float*)d_out;

    float *pt;
    __half *pah,*pch,*pqh,*pkh,*pvth,*pfh,*pwh;
    cudaGetSymbolAddress((void**)&pt,g_t);
    cudaGetSymbolAddress((void**)&pah,g_ah); cudaGetSymbolAddress((void**)&pch,g_ch);
    cudaGetSymbolAddress((void**)&pqh,g_qh);
    cudaGetSymbolAddress((void**)&pkh,g_kh);
    cudaGetSymbolAddress((void**)&pvth,g_vth);
    cudaGetSymbolAddress((void**)&pfh,g_fh);
    cudaGetSymbolAddress((void**)&pwh,g_wh);

    cudaFuncSetAttribute(mma_gemm, cudaFuncAttributeMaxDynamicSharedMemorySize, SMEMSZ);
    cudaFuncSetAttribute(flash_kernel, cudaFuncAttributeMaxDynamicSharedMemorySize, FSMEM);

    dim3 gFl(Ss/128, Bb*NHh);

    embed_kernel<<<Mm,256>>>(ids,tt,imp,noi,we,pe,te,elng,elnb);
    w_stage_all<<<82944,256>>>(Wq,Wk,Wv,Wo,Wi,Wd, pwh);

    for(int l=0;l<Ll;l++){
        size_t wl=(size_t)l*WLSTR, oH=(size_t)l*Hh, oF=(size_t)l*FFf;
        mma_gemm<<<GRIDP,256,SMEMSZ>>>(pah, pwh+wl+OQW,
                                       bq+oH, bk+oH, bv+oH,
                                       0, pqh, pkh, pvth, Mm, 2304, Hh, 7);
        flash_kernel<<<gFl,256,FSMEM>>>(pqh, pkh, pvth, mask, pch);
        mma_gemm<<<GRIDP,256,SMEMSZ>>>(pch, pwh+wl+OOW,
                                       bo+oH, 0,0, pt, 0, 0,0, Mm, Hh, Hh, 0);
        add_ln_kernel<<<Mm,192>>>(pt, g1+oH, b1+oH);
        mma_gemm<<<GRIDP,256,SMEMSZ>>>(pah, pwh+wl+OIW,
                                       bi+oF, 0,0, 0, pfh, 0,0, Mm, FFf, Hh, 3);
        mma_gemm<<<GRIDP,256,SMEMSZ>>>(pfh, pwh+wl+ODW,
                                       bd+oH, 0,0, pt, 0, 0,0, Mm, Hh, FFf, 0);
        add_ln_kernel<<<Mm,192>>>(pt, g2+oH, b2+oH);
    }

    copy_x_kernel<<<(Mm*Hh)/256,256>>>(out);
    pooler_kernel<<<dim3(Hh/256,Bb),256>>>(pw, pb, out+(size_t)Mm*Hh);
}